// round 13
// baseline (speedup 1.0000x reference)
#include <cuda_runtime.h>
#include <cuda_fp16.h>
#include <math.h>

#define D_MODEL 768
#define NHEAD 12
#define HD 64
#define BATCH 2
#define SEQ 2048
#define MROWS (BATCH*SEQ)   // 4096
#define NBH (BATCH*NHEAD)   // 24

// -------- scratch (fp16; no allocations) --------
__device__ __half g_Q[NBH*SEQ*HD];
__device__ __half g_K[NBH*SEQ*HD];
__device__ __half g_V[NBH*SEQ*HD];
__device__ __half g_ctx[MROWS*D_MODEL];
__device__ __half g_xh[MROWS*D_MODEL];
__device__ __half g_Wqh[D_MODEL*D_MODEL];
__device__ __half g_Wkh[D_MODEL*D_MODEL];
__device__ __half g_Wvh[D_MODEL*D_MODEL];
__device__ __half g_Woh[D_MODEL*D_MODEL];

// -------- helpers --------
__device__ __forceinline__ unsigned smem_u32(const void* p) {
    return (unsigned)__cvta_generic_to_shared(p);
}
__device__ __forceinline__ unsigned pack2(float a, float b) {
    __half2 h = __floats2half2_rn(a, b);
    return *reinterpret_cast<unsigned*>(&h);
}
__device__ __forceinline__ float ex2f(float x) {
    float r; asm("ex2.approx.f32 %0, %1;" : "=f"(r) : "f"(x)); return r;
}
__device__ __forceinline__ void ldm4(unsigned& r0, unsigned& r1, unsigned& r2, unsigned& r3,
                                     unsigned addr) {
    asm volatile("ldmatrix.sync.aligned.m8n8.x4.shared.b16 {%0,%1,%2,%3},[%4];"
                 : "=r"(r0), "=r"(r1), "=r"(r2), "=r"(r3) : "r"(addr));
}
__device__ __forceinline__ void ldm4t(unsigned& r0, unsigned& r1, unsigned& r2, unsigned& r3,
                                      unsigned addr) {
    asm volatile("ldmatrix.sync.aligned.m8n8.x4.trans.shared.b16 {%0,%1,%2,%3},[%4];"
                 : "=r"(r0), "=r"(r1), "=r"(r2), "=r"(r3) : "r"(addr));
}
__device__ __forceinline__ void mma16816(float* c, const unsigned* a, unsigned b0, unsigned b1) {
    asm volatile(
        "mma.sync.aligned.m16n8k16.row.col.f32.f16.f16.f32 "
        "{%0,%1,%2,%3},{%4,%5,%6,%7},{%8,%9},{%0,%1,%2,%3};"
        : "+f"(c[0]), "+f"(c[1]), "+f"(c[2]), "+f"(c[3])
        : "r"(a[0]), "r"(a[1]), "r"(a[2]), "r"(a[3]), "r"(b0), "r"(b1));
}
__device__ __forceinline__ void cp16(unsigned dst, const void* src) {
    asm volatile("cp.async.cg.shared.global [%0], [%1], 16;" :: "r"(dst), "l"(src));
}
__device__ __forceinline__ void cp_commit() { asm volatile("cp.async.commit_group;"); }
__device__ __forceinline__ void cp_wait2() { asm volatile("cp.async.wait_group 2;"); }
__device__ __forceinline__ void cp_wait1() { asm volatile("cp.async.wait_group 1;"); }

// ============================================================
// fused fp32 -> fp16 conversion of x + all 4 weights
// ============================================================
#define N8X (MROWS*D_MODEL/8)
#define N8W (D_MODEL*D_MODEL/8)
#define N8TOT (N8X + 4*N8W)

__global__ __launch_bounds__(256) void cvt_all(
    const float* __restrict__ x,
    const float* __restrict__ wq, const float* __restrict__ wk,
    const float* __restrict__ wv, const float* __restrict__ wo,
    __half* __restrict__ xh,
    __half* __restrict__ wqh, __half* __restrict__ wkh,
    __half* __restrict__ wvh, __half* __restrict__ woh)
{
    int i = blockIdx.x * 256 + threadIdx.x;
    if (i >= N8TOT) return;
    const float* src;
    __half* dst;
    int off;
    if (i < N8X) { src = x; dst = xh; off = i; }
    else {
        int j = i - N8X;
        int seg = j / N8W;
        off = j - seg * N8W;
        src = (seg == 0) ? wq : (seg == 1) ? wk : (seg == 2) ? wv : wo;
        dst = (seg == 0) ? wqh : (seg == 1) ? wkh : (seg == 2) ? wvh : woh;
    }
    float4 a = *(const float4*)&src[(size_t)off * 8];
    float4 b = *(const float4*)&src[(size_t)off * 8 + 4];
    uint4 h;
    h.x = pack2(a.x, a.y); h.y = pack2(a.z, a.w);
    h.z = pack2(b.x, b.y); h.w = pack2(b.z, b.w);
    *(uint4*)&dst[(size_t)off * 8] = h;
}

// ============================================================
// fp16 GEMM (R11 config): 128m x 128n block, k-slab 64,
// 3-stage cp.async ring, 256 thr = 8 warps (4m x 2n).
// ============================================================
#define ALD 72
#define BLD 136
#define GSTAGE (128*ALD + 64*BLD)     // halves per stage
#define G_SMEM (3 * GSTAGE * 2)       // bytes

template<bool OUT_HALF, bool SCATTER>
__device__ __forceinline__ void gemm_body(
    const __half* __restrict__ X, const __half* __restrict__ W,
    const float* __restrict__ bias, void* __restrict__ outp, float oscale,
    int row0, int col0)
{
    extern __shared__ __half gsm[];

    const int tid = threadIdx.x;
    const int lane = tid & 31;
    const int g = lane >> 2;
    const int t = lane & 3;
    const int wid = tid >> 5;
    const int wm = (wid & 3) * 32;
    const int wn = (wid >> 2) * 64;

    float acc[2][8][4];
#pragma unroll
    for (int i = 0; i < 2; i++)
#pragma unroll
        for (int j = 0; j < 8; j++)
#pragma unroll
            for (int k = 0; k < 4; k++) acc[i][j][k] = 0.f;

    auto submit = [&](int slab, int st) {
        const int k0 = slab * 64;
        __half* As = gsm + st * GSTAGE;
        __half* Bs = As + 128 * ALD;
#pragma unroll
        for (int i = 0; i < 4; i++) {
            int ci = tid + 256 * i;
            int ar = ci >> 3, ac = (ci & 7) * 8;
            cp16(smem_u32(&As[ar * ALD + ac]),
                 &X[(size_t)(row0 + ar) * 768 + k0 + ac]);
        }
#pragma unroll
        for (int i = 0; i < 4; i++) {
            int ci = tid + 256 * i;
            int br = ci >> 4, bc = (ci & 15) * 8;
            cp16(smem_u32(&Bs[br * BLD + bc]),
                 &W[(size_t)(k0 + br) * 768 + col0 + bc]);
        }
        cp_commit();
    };

    const int NS = 768 / 64;    // 12
    submit(0, 0);
    submit(1, 1);

    for (int s = 0; s < NS; s++) {
        const int st = s % 3;
        cp_wait1();
        __syncthreads();
        if (s + 2 < NS) submit(s + 2, (s + 2) % 3);

        const __half* As = gsm + st * GSTAGE;
        const __half* Bs = As + 128 * ALD;

#pragma unroll
        for (int ks = 0; ks < 4; ks++) {
            unsigned a[2][4];
#pragma unroll
            for (int mt = 0; mt < 2; mt++)
                ldm4(a[mt][0], a[mt][1], a[mt][2], a[mt][3],
                     smem_u32(&As[(wm + mt * 16 + (lane & 15)) * ALD +
                                  ks * 16 + ((lane >> 4) << 3)]));
            unsigned b[4][4];
#pragma unroll
            for (int np = 0; np < 4; np++)
                ldm4t(b[np][0], b[np][1], b[np][2], b[np][3],
                      smem_u32(&Bs[(ks * 16 + (lane & 7) + ((lane >> 3) & 1) * 8) * BLD +
                                   wn + np * 16 + (lane >> 4) * 8]));
#pragma unroll
            for (int mt = 0; mt < 2; mt++)
#pragma unroll
                for (int np = 0; np < 4; np++) {
                    mma16816(acc[mt][np * 2], a[mt], b[np][0], b[np][1]);
                    mma16816(acc[mt][np * 2 + 1], a[mt], b[np][2], b[np][3]);
                }
        }
    }

#pragma unroll
    for (int nt = 0; nt < 8; nt++) {
        int col = col0 + wn + nt * 8 + 2 * t;
        float b0 = bias[col], b1 = bias[col + 1];
#pragma unroll
        for (int mt = 0; mt < 2; mt++)
#pragma unroll
            for (int hh = 0; hh < 2; hh++) {
                int m = row0 + wm + mt * 16 + g + hh * 8;
                float v0 = (acc[mt][nt][hh * 2] + b0) * oscale;
                float v1 = (acc[mt][nt][hh * 2 + 1] + b1) * oscale;
                if constexpr (OUT_HALF) {
                    __half* oh = (__half*)outp;
                    size_t idx;
                    if constexpr (SCATTER) {
                        int head = col >> 6, d = col & 63;
                        int bb = m >> 11, ss = m & 2047;
                        idx = ((size_t)(bb * NHEAD + head) * SEQ + ss) * HD + d;
                    } else {
                        idx = (size_t)m * 768 + col;
                    }
                    *(__half2*)&oh[idx] = __floats2half2_rn(v0, v1);
                } else {
                    float* of = (float*)outp;
                    float2 o; o.x = v0; o.y = v1;
                    *(float2*)&of[(size_t)m * 768 + col] = o;
                }
            }
    }
}

__global__ __launch_bounds__(256, 2) void gemm_qkv(
    const __half* __restrict__ X,
    const __half* __restrict__ Wq, const __half* __restrict__ Wk,
    const __half* __restrict__ Wv,
    const float* __restrict__ bq, const float* __restrict__ bk,
    const float* __restrict__ bv,
    __half* __restrict__ Qo, __half* __restrict__ Ko, __half* __restrict__ Vo,
    float qscale)
{
    const int z = blockIdx.z;
    const __half* W = (z == 0) ? Wq : (z == 1) ? Wk : Wv;
    const float* b  = (z == 0) ? bq : (z == 1) ? bk : bv;
    __half* o       = (z == 0) ? Qo : (z == 1) ? Ko : Vo;
    float sc        = (z == 0) ? qscale : 1.0f;
    gemm_body<true, true>(X, W, b, o, sc, blockIdx.y * 128, blockIdx.x * 128);
}

__global__ __launch_bounds__(256, 2) void gemm_out(
    const __half* __restrict__ X, const __half* __restrict__ W,
    const float* __restrict__ bias, float* __restrict__ out)
{
    gemm_body<false, false>(X, W, bias, out, 1.0f, blockIdx.y * 128, blockIdx.x * 128);
}

// ============================================================
// fp16 flash attention: q-tile 128, 4 warps x 32 q-rows,
// 64-key tiles, 3-stage cp.async ring, 3 CTAs/SM (single wave).
// ============================================================
#define QLD 72
#define KVLD 72
#define ATHREADS 128
#define KVSTAGES 3

__global__ __launch_bounds__(ATHREADS, 3) void attn_f16(
    const __half* __restrict__ Qg, const __half* __restrict__ Kg,
    const __half* __restrict__ Vg, __half* __restrict__ ctx)
{
    extern __shared__ __half sm[];
    __half* Qs = sm;
    __half* KV = sm + 128 * QLD;

    const int tid = threadIdx.x;
    const int lane = tid & 31;
    const int g = lane >> 2;
    const int t = lane & 3;
    const int wid = tid >> 5;
    const int qr = wid * 32;
    const int bh = blockIdx.y;
    const int qt = blockIdx.x;

    const __half* Qp = Qg + ((size_t)bh * SEQ + qt * 128) * HD;
    const __half* Kbase = Kg + (size_t)bh * SEQ * HD;
    const __half* Vbase = Vg + (size_t)bh * SEQ * HD;

    const int NT = SEQ / 64;

    auto submit = [&](int kt, int st) {
        const __half* Kp = Kbase + (size_t)kt * 64 * HD;
        const __half* Vp = Vbase + (size_t)kt * 64 * HD;
        __half* Kd = KV + st * 2 * 64 * KVLD;
        __half* Vd = Kd + 64 * KVLD;
#pragma unroll
        for (int i = 0; i < 4; i++) {
            int ci = tid + ATHREADS * i;
            int row = ci >> 3, c = ci & 7;
            cp16(smem_u32(&Kd[row * KVLD + c * 8]), &Kp[(size_t)row * HD + c * 8]);
            cp16(smem_u32(&Vd[row * KVLD + c * 8]), &Vp[(size_t)row * HD + c * 8]);
        }
        cp_commit();
    };

    submit(0, 0);
    submit(1, 1);
#pragma unroll
    for (int i = 0; i < 8; i++) {
        int ci = tid + ATHREADS * i;
        int row = ci >> 3, c = ci & 7;
        *(uint4*)&Qs[row * QLD + c * 8] = *(const uint4*)&Qp[(size_t)row * HD + c * 8];
    }
    __syncthreads();

    unsigned qa[2][4][4];
#pragma unroll
    for (int mt = 0; mt < 2; mt++)
#pragma unroll
        for (int ks = 0; ks < 4; ks++)
            ldm4(qa[mt][ks][0], qa[mt][ks][1], qa[mt][ks][2], qa[mt][ks][3],
                 smem_u32(&Qs[(qr + mt * 16 + (lane & 15)) * QLD +
                              ks * 16 + ((lane >> 4) << 3)]));

    float acc[2][8][4];
    float rowm[2][2], rowl[2][2];
#pragma unroll
    for (int mt = 0; mt < 2; mt++) {
#pragma unroll
        for (int hh = 0; hh < 2; hh++) { rowm[mt][hh] = -1e30f; rowl[mt][hh] = 0.f; }
#pragma unroll
        for (int i = 0; i < 8; i++)
#pragma unroll
            for (int j = 0; j < 4; j++) acc[mt][i][j] = 0.f;
    }

    for (int kt = 0; kt < NT; kt++) {
        const int s = kt % KVSTAGES;
        cp_wait1();
        __syncthreads();
        if (kt + 2 < NT) submit(kt + 2, (kt + 2) % KVSTAGES);

        const __half* Kd = KV + s * 2 * 64 * KVLD;
        const __half* Vd = Kd + 64 * KVLD;

        float sc[2][8][4];
#pragma unroll
        for (int mt = 0; mt < 2; mt++)
#pragma unroll
            for (int i = 0; i < 8; i++)
#pragma unroll
                for (int j = 0; j < 4; j++) sc[mt][i][j] = 0.f;

#pragma unroll
        for (int ks = 0; ks < 4; ks++) {
            unsigned kb[4][4];
#pragma unroll
            for (int kp = 0; kp < 4; kp++)
                ldm4(kb[kp][0], kb[kp][1], kb[kp][2], kb[kp][3],
                     smem_u32(&Kd[(kp * 16 + (lane & 15)) * KVLD +
                                  ks * 16 + ((lane >> 4) << 3)]));
#pragma unroll
            for (int kp = 0; kp < 4; kp++)
#pragma unroll
                for (int mt = 0; mt < 2; mt++) {
                    mma16816(sc[mt][kp * 2],     qa[mt][ks], kb[kp][0], kb[kp][2]);
                    mma16816(sc[mt][kp * 2 + 1], qa[mt][ks], kb[kp][1], kb[kp][3]);
                }
        }

        float newm[2][2], corr[2][2];
#pragma unroll
        for (int mt = 0; mt < 2; mt++)
#pragma unroll
            for (int hh = 0; hh < 2; hh++) {
                float mx = -1e30f;
#pragma unroll
                for (int nt = 0; nt < 8; nt++)
                    mx = fmaxf(mx, fmaxf(sc[mt][nt][hh * 2], sc[mt][nt][hh * 2 + 1]));
                mx = fmaxf(mx, __shfl_xor_sync(0xffffffffu, mx, 1));
                mx = fmaxf(mx, __shfl_xor_sync(0xffffffffu, mx, 2));
                newm[mt][hh] = fmaxf(rowm[mt][hh], mx);
                corr[mt][hh] = ex2f(rowm[mt][hh] - newm[mt][hh]);
                rowm[mt][hh] = newm[mt][hh];
#pragma unroll
                for (int nt = 0; nt < 8; nt++) {
                    acc[mt][nt][hh * 2] *= corr[mt][hh];
                    acc[mt][nt][hh * 2 + 1] *= corr[mt][hh];
                }
            }

        unsigned ph[2][4][4];
#pragma unroll
        for (int mt = 0; mt < 2; mt++) {
            float ps0 = 0.f, ps1 = 0.f;
#pragma unroll
            for (int nt = 0; nt < 8; nt++) {
                __half2 e0 = h2exp2(__floats2half2_rn(sc[mt][nt][0] - newm[mt][0],
                                                      sc[mt][nt][1] - newm[mt][0]));
                __half2 e1 = h2exp2(__floats2half2_rn(sc[mt][nt][2] - newm[mt][1],
                                                      sc[mt][nt][3] - newm[mt][1]));
                ph[mt][nt >> 1][(nt & 1) * 2]     = *reinterpret_cast<unsigned*>(&e0);
                ph[mt][nt >> 1][(nt & 1) * 2 + 1] = *reinterpret_cast<unsigned*>(&e1);
                float2 f0 = __half22float2(e0);
                float2 f1 = __half22float2(e1);
                ps0 += f0.x + f0.y;
                ps1 += f1.x + f1.y;
            }
            ps0 += __shfl_xor_sync(0xffffffffu, ps0, 1);
            ps0 += __shfl_xor_sync(0xffffffffu, ps0, 2);
            ps1 += __shfl_xor_sync(0xffffffffu, ps1, 1);
            ps1 += __shfl_xor_sync(0xffffffffu, ps1, 2);
            rowl[mt][0] = rowl[mt][0] * corr[mt][0] + ps0;
            rowl[mt][1] = rowl[mt][1] * corr[mt][1] + ps1;
        }

#pragma unroll
        for (int ks = 0; ks < 4; ks++) {
            unsigned vb[4][4];
#pragma unroll
            for (int dp = 0; dp < 4; dp++)
                ldm4t(vb[dp][0], vb[dp][1], vb[dp][2], vb[dp][3],
                      smem_u32(&Vd[(ks * 16 + (lane & 7) + ((lane >> 3) & 1) * 8) * KVLD +
                                   dp * 16 + (lane >> 4) * 8]));
#pragma unroll
            for (int dp = 0; dp < 4; dp++)
#pragma unroll
                for (int mt = 0; mt < 2; mt++) {
                    mma16816(acc[mt][dp * 2],     ph[mt][ks], vb[dp][0], vb[dp][1]);
                    mma16816(acc[mt][dp * 2 + 1], ph[mt][ks], vb[dp][2], vb[dp][3]);
                }
        }
    }

    const int bb = bh / NHEAD;
    const int head = bh % NHEAD;
#pragma unroll
    for (int mt = 0; mt < 2; mt++)
#pragma unroll
        for (int hh = 0; hh < 2; hh++) {
            int q = qt * 128 + qr + mt * 16 + g + hh * 8;
            float inv = 1.f / rowl[mt][hh];
#pragma unroll
            for (int nt = 0; nt < 8; nt++) {
                int d = nt * 8 + 2 * t;
                *(__half2*)&ctx[(size_t)(bb * SEQ + q) * D_MODEL + head * HD + d] =
                    __floats2half2_rn(acc[mt][nt][hh * 2] * inv,
                                      acc[mt][nt][hh * 2 + 1] * inv);
            }
        }
}

// ============================================================
extern "C" void kernel_launch(void* const* d_in, const int* in_sizes, int n_in,
                              void* d_out, int out_size)
{
    const float* x  = (const float*)d_in[0];
    const float* Wq = (const float*)d_in[1];
    const float* bq = (const float*)d_in[2];
    const float* Wk = (const float*)d_in[3];
    const float* bk = (const float*)d_in[4];
    const float* Wv = (const float*)d_in[5];
    const float* bv = (const float*)d_in[6];
    const float* Wo = (const float*)d_in[7];
    const float* bo = (const float*)d_in[8];
    float* out = (float*)d_out;

    __half *Qp, *Kp, *Vp, *ctxp, *xh, *Wqh, *Wkh, *Wvh, *Woh;
    cudaGetSymbolAddress((void**)&Qp, g_Q);
    cudaGetSymbolAddress((void**)&Kp, g_K);
    cudaGetSymbolAddress((void**)&Vp, g_V);
    cudaGetSymbolAddress((void**)&ctxp, g_ctx);
    cudaGetSymbolAddress((void**)&xh, g_xh);
    cudaGetSymbolAddress((void**)&Wqh, g_Wqh);
    cudaGetSymbolAddress((void**)&Wkh, g_Wkh);
    cudaGetSymbolAddress((void**)&Wvh, g_Wvh);
    cudaGetSymbolAddress((void**)&Woh, g_Woh);

    const size_t attn_smem =
        (size_t)(128 * QLD + 2 * KVSTAGES * 64 * KVLD) * sizeof(__half);   // 73728 B
    cudaFuncSetAttribute(attn_f16, cudaFuncAttributeMaxDynamicSharedMemorySize,
                         (int)attn_smem);
    cudaFuncSetAttribute(gemm_qkv, cudaFuncAttributeMaxDynamicSharedMemorySize, G_SMEM);
    cudaFuncSetAttribute(gemm_out, cudaFuncAttributeMaxDynamicSharedMemorySize, G_SMEM);

    cvt_all<<<(N8TOT + 255) / 256, 256>>>(x, Wq, Wk, Wv, Wo,
                                          xh, Wqh, Wkh, Wvh, Woh);

    const float QSCALE = 0.125f * 1.4426950408889634f;
    dim3 gq(768 / 128, MROWS / 128, 3);   // (6, 32, 3)
    gemm_qkv<<<gq, 256, G_SMEM>>>(xh, Wqh, Wkh, Wvh, bq, bk, bv, Qp, Kp, Vp, QSCALE);

    dim3 ga(SEQ / 128, NBH);              // (16, 24)
    attn_f16<<<ga, ATHREADS, attn_smem>>>(Qp, Kp, Vp, ctxp);

    dim3 gg(768 / 128, MROWS / 128);      // (6, 32)
    gemm_out<<<gg, 256, G_SMEM>>>(ctxp, Woh, bo, out);
}

// round 14
// speedup vs baseline: 1.0587x; 1.0587x over previous
#include <cuda_runtime.h>
#include <cuda_fp16.h>
#include <math.h>

#define D_MODEL 768
#define NHEAD 12
#define HD 64
#define BATCH 2
#define SEQ 2048
#define MROWS (BATCH*SEQ)   // 4096
#define NBH (BATCH*NHEAD)   // 24

// -------- scratch (fp16; no allocations) --------
__device__ __half g_Q[NBH*SEQ*HD];
__device__ __half g_K[NBH*SEQ*HD];
__device__ __half g_V[NBH*SEQ*HD];
__device__ __half g_ctx[MROWS*D_MODEL];
__device__ __half g_xh[MROWS*D_MODEL];
__device__ __half g_Wqh[D_MODEL*D_MODEL];
__device__ __half g_Wkh[D_MODEL*D_MODEL];
__device__ __half g_Wvh[D_MODEL*D_MODEL];
__device__ __half g_Woh[D_MODEL*D_MODEL];

// -------- helpers --------
__device__ __forceinline__ unsigned smem_u32(const void* p) {
    return (unsigned)__cvta_generic_to_shared(p);
}
__device__ __forceinline__ unsigned pack2(float a, float b) {
    __half2 h = __floats2half2_rn(a, b);
    return *reinterpret_cast<unsigned*>(&h);
}
__device__ __forceinline__ float ex2f(float x) {
    float r; asm("ex2.approx.f32 %0, %1;" : "=f"(r) : "f"(x)); return r;
}
__device__ __forceinline__ void ldm4(unsigned& r0, unsigned& r1, unsigned& r2, unsigned& r3,
                                     unsigned addr) {
    asm volatile("ldmatrix.sync.aligned.m8n8.x4.shared.b16 {%0,%1,%2,%3},[%4];"
                 : "=r"(r0), "=r"(r1), "=r"(r2), "=r"(r3) : "r"(addr));
}
__device__ __forceinline__ void ldm4t(unsigned& r0, unsigned& r1, unsigned& r2, unsigned& r3,
                                      unsigned addr) {
    asm volatile("ldmatrix.sync.aligned.m8n8.x4.trans.shared.b16 {%0,%1,%2,%3},[%4];"
                 : "=r"(r0), "=r"(r1), "=r"(r2), "=r"(r3) : "r"(addr));
}
__device__ __forceinline__ void mma16816(float* c, const unsigned* a, unsigned b0, unsigned b1) {
    asm volatile(
        "mma.sync.aligned.m16n8k16.row.col.f32.f16.f16.f32 "
        "{%0,%1,%2,%3},{%4,%5,%6,%7},{%8,%9},{%0,%1,%2,%3};"
        : "+f"(c[0]), "+f"(c[1]), "+f"(c[2]), "+f"(c[3])
        : "r"(a[0]), "r"(a[1]), "r"(a[2]), "r"(a[3]), "r"(b0), "r"(b1));
}
__device__ __forceinline__ void cp16(unsigned dst, const void* src) {
    asm volatile("cp.async.cg.shared.global [%0], [%1], 16;" :: "r"(dst), "l"(src));
}
__device__ __forceinline__ void cp_commit() { asm volatile("cp.async.commit_group;"); }
__device__ __forceinline__ void cp_wait2() { asm volatile("cp.async.wait_group 2;"); }
__device__ __forceinline__ void cp_wait1() { asm volatile("cp.async.wait_group 1;"); }

// ============================================================
// fused fp32 -> fp16 conversion, 16 elems/thread
// ============================================================
#define N16X (MROWS*D_MODEL/16)
#define N16W (D_MODEL*D_MODEL/16)
#define N16TOT (N16X + 4*N16W)

__global__ __launch_bounds__(256) void cvt_all(
    const float* __restrict__ x,
    const float* __restrict__ wq, const float* __restrict__ wk,
    const float* __restrict__ wv, const float* __restrict__ wo,
    __half* __restrict__ xh,
    __half* __restrict__ wqh, __half* __restrict__ wkh,
    __half* __restrict__ wvh, __half* __restrict__ woh)
{
    int i = blockIdx.x * 256 + threadIdx.x;
    if (i >= N16TOT) return;
    const float* src;
    __half* dst;
    int off;
    if (i < N16X) { src = x; dst = xh; off = i; }
    else {
        int j = i - N16X;
        int seg = j / N16W;
        off = j - seg * N16W;
        src = (seg == 0) ? wq : (seg == 1) ? wk : (seg == 2) ? wv : wo;
        dst = (seg == 0) ? wqh : (seg == 1) ? wkh : (seg == 2) ? wvh : woh;
    }
#pragma unroll
    for (int h = 0; h < 2; h++) {
        float4 a = *(const float4*)&src[(size_t)off * 16 + h * 8];
        float4 b = *(const float4*)&src[(size_t)off * 16 + h * 8 + 4];
        uint4 hv;
        hv.x = pack2(a.x, a.y); hv.y = pack2(a.z, a.w);
        hv.z = pack2(b.x, b.y); hv.w = pack2(b.z, b.w);
        *(uint4*)&dst[(size_t)off * 16 + h * 8] = hv;
    }
}

// ============================================================
// fp16 GEMM (R11/R12 config): 128m x 128n block, k-slab 64,
// 3-stage cp.async ring, 256 thr = 8 warps (4m x 2n).
// ============================================================
#define ALD 72
#define BLD 136
#define GSTAGE (128*ALD + 64*BLD)
#define G_SMEM (3 * GSTAGE * 2)

template<bool OUT_HALF, bool SCATTER>
__device__ __forceinline__ void gemm_body(
    const __half* __restrict__ X, const __half* __restrict__ W,
    const float* __restrict__ bias, void* __restrict__ outp, float oscale,
    int row0, int col0)
{
    extern __shared__ __half gsm[];

    const int tid = threadIdx.x;
    const int lane = tid & 31;
    const int g = lane >> 2;
    const int t = lane & 3;
    const int wid = tid >> 5;
    const int wm = (wid & 3) * 32;
    const int wn = (wid >> 2) * 64;

    float acc[2][8][4];
#pragma unroll
    for (int i = 0; i < 2; i++)
#pragma unroll
        for (int j = 0; j < 8; j++)
#pragma unroll
            for (int k = 0; k < 4; k++) acc[i][j][k] = 0.f;

    auto submit = [&](int slab, int st) {
        const int k0 = slab * 64;
        __half* As = gsm + st * GSTAGE;
        __half* Bs = As + 128 * ALD;
#pragma unroll
        for (int i = 0; i < 4; i++) {
            int ci = tid + 256 * i;
            int ar = ci >> 3, ac = (ci & 7) * 8;
            cp16(smem_u32(&As[ar * ALD + ac]),
                 &X[(size_t)(row0 + ar) * 768 + k0 + ac]);
        }
#pragma unroll
        for (int i = 0; i < 4; i++) {
            int ci = tid + 256 * i;
            int br = ci >> 4, bc = (ci & 15) * 8;
            cp16(smem_u32(&Bs[br * BLD + bc]),
                 &W[(size_t)(k0 + br) * 768 + col0 + bc]);
        }
        cp_commit();
    };

    const int NS = 768 / 64;
    submit(0, 0);
    submit(1, 1);

    for (int s = 0; s < NS; s++) {
        const int st = s % 3;
        cp_wait1();
        __syncthreads();
        if (s + 2 < NS) submit(s + 2, (s + 2) % 3);

        const __half* As = gsm + st * GSTAGE;
        const __half* Bs = As + 128 * ALD;

#pragma unroll
        for (int ks = 0; ks < 4; ks++) {
            unsigned a[2][4];
#pragma unroll
            for (int mt = 0; mt < 2; mt++)
                ldm4(a[mt][0], a[mt][1], a[mt][2], a[mt][3],
                     smem_u32(&As[(wm + mt * 16 + (lane & 15)) * ALD +
                                  ks * 16 + ((lane >> 4) << 3)]));
            unsigned b[4][4];
#pragma unroll
            for (int np = 0; np < 4; np++)
                ldm4t(b[np][0], b[np][1], b[np][2], b[np][3],
                      smem_u32(&Bs[(ks * 16 + (lane & 7) + ((lane >> 3) & 1) * 8) * BLD +
                                   wn + np * 16 + (lane >> 4) * 8]));
#pragma unroll
            for (int mt = 0; mt < 2; mt++)
#pragma unroll
                for (int np = 0; np < 4; np++) {
                    mma16816(acc[mt][np * 2], a[mt], b[np][0], b[np][1]);
                    mma16816(acc[mt][np * 2 + 1], a[mt], b[np][2], b[np][3]);
                }
        }
    }

#pragma unroll
    for (int nt = 0; nt < 8; nt++) {
        int col = col0 + wn + nt * 8 + 2 * t;
        float b0 = bias[col], b1 = bias[col + 1];
#pragma unroll
        for (int mt = 0; mt < 2; mt++)
#pragma unroll
            for (int hh = 0; hh < 2; hh++) {
                int m = row0 + wm + mt * 16 + g + hh * 8;
                float v0 = (acc[mt][nt][hh * 2] + b0) * oscale;
                float v1 = (acc[mt][nt][hh * 2 + 1] + b1) * oscale;
                if constexpr (OUT_HALF) {
                    __half* oh = (__half*)outp;
                    size_t idx;
                    if constexpr (SCATTER) {
                        int head = col >> 6, d = col & 63;
                        int bb = m >> 11, ss = m & 2047;
                        idx = ((size_t)(bb * NHEAD + head) * SEQ + ss) * HD + d;
                    } else {
                        idx = (size_t)m * 768 + col;
                    }
                    *(__half2*)&oh[idx] = __floats2half2_rn(v0, v1);
                } else {
                    float* of = (float*)outp;
                    float2 o; o.x = v0; o.y = v1;
                    *(float2*)&of[(size_t)m * 768 + col] = o;
                }
            }
    }
}

__global__ __launch_bounds__(256, 2) void gemm_qkv(
    const __half* __restrict__ X,
    const __half* __restrict__ Wq, const __half* __restrict__ Wk,
    const __half* __restrict__ Wv,
    const float* __restrict__ bq, const float* __restrict__ bk,
    const float* __restrict__ bv,
    __half* __restrict__ Qo, __half* __restrict__ Ko, __half* __restrict__ Vo,
    float qscale)
{
    const int z = blockIdx.z;
    const __half* W = (z == 0) ? Wq : (z == 1) ? Wk : Wv;
    const float* b  = (z == 0) ? bq : (z == 1) ? bk : bv;
    __half* o       = (z == 0) ? Qo : (z == 1) ? Ko : Vo;
    float sc        = (z == 0) ? qscale : 1.0f;
    gemm_body<true, true>(X, W, b, o, sc, blockIdx.y * 128, blockIdx.x * 128);
}

__global__ __launch_bounds__(256, 2) void gemm_out(
    const __half* __restrict__ X, const __half* __restrict__ W,
    const float* __restrict__ bias, float* __restrict__ out)
{
    gemm_body<false, false>(X, W, bias, out, 1.0f, blockIdx.y * 128, blockIdx.x * 128);
}

// ============================================================
// fp16 flash attention (R12 config): q-tile 128, 4 warps x 32 q,
// 64-key tiles, 4-stage cp.async ring, Q staged via cp.async.
// ============================================================
#define QLD 72
#define KVLD 72
#define ATHREADS 128
#define KVSTAGES 4

__global__ __launch_bounds__(ATHREADS, 2) void attn_f16(
    const __half* __restrict__ Qg, const __half* __restrict__ Kg,
    const __half* __restrict__ Vg, __half* __restrict__ ctx)
{
    extern __shared__ __half sm[];
    __half* Qs = sm;
    __half* KV = sm + 128 * QLD;

    const int tid = threadIdx.x;
    const int lane = tid & 31;
    const int g = lane >> 2;
    const int t = lane & 3;
    const int wid = tid >> 5;
    const int qr = wid * 32;
    const int bh = blockIdx.y;
    const int qt = blockIdx.x;

    const __half* Qp = Qg + ((size_t)bh * SEQ + qt * 128) * HD;
    const __half* Kbase = Kg + (size_t)bh * SEQ * HD;
    const __half* Vbase = Vg + (size_t)bh * SEQ * HD;

    const int NT = SEQ / 64;

    auto submit = [&](int kt, int st) {
        const __half* Kp = Kbase + (size_t)kt * 64 * HD;
        const __half* Vp = Vbase + (size_t)kt * 64 * HD;
        __half* Kd = KV + st * 2 * 64 * KVLD;
        __half* Vd = Kd + 64 * KVLD;
#pragma unroll
        for (int i = 0; i < 4; i++) {
            int ci = tid + ATHREADS * i;
            int row = ci >> 3, c = ci & 7;
            cp16(smem_u32(&Kd[row * KVLD + c * 8]), &Kp[(size_t)row * HD + c * 8]);
            cp16(smem_u32(&Vd[row * KVLD + c * 8]), &Vp[(size_t)row * HD + c * 8]);
        }
        cp_commit();
    };

    // Q as its own cp.async group (group 0), then 3 KV prefetch groups.
    // First-loop cp_wait2 leaves <=2 groups outstanding -> Q + tile0 complete.
#pragma unroll
    for (int i = 0; i < 8; i++) {
        int ci = tid + ATHREADS * i;
        int row = ci >> 3, c = ci & 7;
        cp16(smem_u32(&Qs[row * QLD + c * 8]), &Qp[(size_t)row * HD + c * 8]);
    }
    cp_commit();
    submit(0, 0);
    submit(1, 1);
    submit(2, 2);

    cp_wait2();            // Q + tile0 landed
    __syncthreads();

    unsigned qa[2][4][4];
#pragma unroll
    for (int mt = 0; mt < 2; mt++)
#pragma unroll
        for (int ks = 0; ks < 4; ks++)
            ldm4(qa[mt][ks][0], qa[mt][ks][1], qa[mt][ks][2], qa[mt][ks][3],
                 smem_u32(&Qs[(qr + mt * 16 + (lane & 15)) * QLD +
                              ks * 16 + ((lane >> 4) << 3)]));

    float acc[2][8][4];
    float rowm[2][2], rowl[2][2];
#pragma unroll
    for (int mt = 0; mt < 2; mt++) {
#pragma unroll
        for (int hh = 0; hh < 2; hh++) { rowm[mt][hh] = -1e30f; rowl[mt][hh] = 0.f; }
#pragma unroll
        for (int i = 0; i < 8; i++)
#pragma unroll
            for (int j = 0; j < 4; j++) acc[mt][i][j] = 0.f;
    }

    for (int kt = 0; kt < NT; kt++) {
        const int s = kt % KVSTAGES;
        cp_wait2();
        __syncthreads();
        if (kt + 3 < NT) submit(kt + 3, (kt + 3) % KVSTAGES);

        const __half* Kd = KV + s * 2 * 64 * KVLD;
        const __half* Vd = Kd + 64 * KVLD;

        float sc[2][8][4];
#pragma unroll
        for (int mt = 0; mt < 2; mt++)
#pragma unroll
            for (int i = 0; i < 8; i++)
#pragma unroll
                for (int j = 0; j < 4; j++) sc[mt][i][j] = 0.f;

#pragma unroll
        for (int ks = 0; ks < 4; ks++) {
            unsigned kb[4][4];
#pragma unroll
            for (int kp = 0; kp < 4; kp++)
                ldm4(kb[kp][0], kb[kp][1], kb[kp][2], kb[kp][3],
                     smem_u32(&Kd[(kp * 16 + (lane & 15)) * KVLD +
                                  ks * 16 + ((lane >> 4) << 3)]));
#pragma unroll
            for (int kp = 0; kp < 4; kp++)
#pragma unroll
                for (int mt = 0; mt < 2; mt++) {
                    mma16816(sc[mt][kp * 2],     qa[mt][ks], kb[kp][0], kb[kp][2]);
                    mma16816(sc[mt][kp * 2 + 1], qa[mt][ks], kb[kp][1], kb[kp][3]);
                }
        }

        float newm[2][2], corr[2][2];
#pragma unroll
        for (int mt = 0; mt < 2; mt++)
#pragma unroll
            for (int hh = 0; hh < 2; hh++) {
                float mx = -1e30f;
#pragma unroll
                for (int nt = 0; nt < 8; nt++)
                    mx = fmaxf(mx, fmaxf(sc[mt][nt][hh * 2], sc[mt][nt][hh * 2 + 1]));
                mx = fmaxf(mx, __shfl_xor_sync(0xffffffffu, mx, 1));
                mx = fmaxf(mx, __shfl_xor_sync(0xffffffffu, mx, 2));
                newm[mt][hh] = fmaxf(rowm[mt][hh], mx);
                corr[mt][hh] = ex2f(rowm[mt][hh] - newm[mt][hh]);
                rowm[mt][hh] = newm[mt][hh];
#pragma unroll
                for (int nt = 0; nt < 8; nt++) {
                    acc[mt][nt][hh * 2] *= corr[mt][hh];
                    acc[mt][nt][hh * 2 + 1] *= corr[mt][hh];
                }
            }

        unsigned ph[2][4][4];
#pragma unroll
        for (int mt = 0; mt < 2; mt++) {
            float ps0 = 0.f, ps1 = 0.f;
#pragma unroll
            for (int nt = 0; nt < 8; nt++) {
                __half2 e0 = h2exp2(__floats2half2_rn(sc[mt][nt][0] - newm[mt][0],
                                                      sc[mt][nt][1] - newm[mt][0]));
                __half2 e1 = h2exp2(__floats2half2_rn(sc[mt][nt][2] - newm[mt][1],
                                                      sc[mt][nt][3] - newm[mt][1]));
                ph[mt][nt >> 1][(nt & 1) * 2]     = *reinterpret_cast<unsigned*>(&e0);
                ph[mt][nt >> 1][(nt & 1) * 2 + 1] = *reinterpret_cast<unsigned*>(&e1);
                float2 f0 = __half22float2(e0);
                float2 f1 = __half22float2(e1);
                ps0 += f0.x + f0.y;
                ps1 += f1.x + f1.y;
            }
            ps0 += __shfl_xor_sync(0xffffffffu, ps0, 1);
            ps0 += __shfl_xor_sync(0xffffffffu, ps0, 2);
            ps1 += __shfl_xor_sync(0xffffffffu, ps1, 1);
            ps1 += __shfl_xor_sync(0xffffffffu, ps1, 2);
            rowl[mt][0] = rowl[mt][0] * corr[mt][0] + ps0;
            rowl[mt][1] = rowl[mt][1] * corr[mt][1] + ps1;
        }

#pragma unroll
        for (int ks = 0; ks < 4; ks++) {
            unsigned vb[4][4];
#pragma unroll
            for (int dp = 0; dp < 4; dp++)
                ldm4t(vb[dp][0], vb[dp][1], vb[dp][2], vb[dp][3],
                      smem_u32(&Vd[(ks * 16 + (lane & 7) + ((lane >> 3) & 1) * 8) * KVLD +
                                   dp * 16 + (lane >> 4) * 8]));
#pragma unroll
            for (int dp = 0; dp < 4; dp++)
#pragma unroll
                for (int mt = 0; mt < 2; mt++) {
                    mma16816(acc[mt][dp * 2],     ph[mt][ks], vb[dp][0], vb[dp][1]);
                    mma16816(acc[mt][dp * 2 + 1], ph[mt][ks], vb[dp][2], vb[dp][3]);
                }
        }
    }

    const int bb = bh / NHEAD;
    const int head = bh % NHEAD;
#pragma unroll
    for (int mt = 0; mt < 2; mt++)
#pragma unroll
        for (int hh = 0; hh < 2; hh++) {
            int q = qt * 128 + qr + mt * 16 + g + hh * 8;
            float inv = 1.f / rowl[mt][hh];
#pragma unroll
            for (int nt = 0; nt < 8; nt++) {
                int d = nt * 8 + 2 * t;
                *(__half2*)&ctx[(size_t)(bb * SEQ + q) * D_MODEL + head * HD + d] =
                    __floats2half2_rn(acc[mt][nt][hh * 2] * inv,
                                      acc[mt][nt][hh * 2 + 1] * inv);
            }
        }
}

// ============================================================
extern "C" void kernel_launch(void* const* d_in, const int* in_sizes, int n_in,
                              void* d_out, int out_size)
{
    const float* x  = (const float*)d_in[0];
    const float* Wq = (const float*)d_in[1];
    const float* bq = (const float*)d_in[2];
    const float* Wk = (const float*)d_in[3];
    const float* bk = (const float*)d_in[4];
    const float* Wv = (const float*)d_in[5];
    const float* bv = (const float*)d_in[6];
    const float* Wo = (const float*)d_in[7];
    const float* bo = (const float*)d_in[8];
    float* out = (float*)d_out;

    __half *Qp, *Kp, *Vp, *ctxp, *xh, *Wqh, *Wkh, *Wvh, *Woh;
    cudaGetSymbolAddress((void**)&Qp, g_Q);
    cudaGetSymbolAddress((void**)&Kp, g_K);
    cudaGetSymbolAddress((void**)&Vp, g_V);
    cudaGetSymbolAddress((void**)&ctxp, g_ctx);
    cudaGetSymbolAddress((void**)&xh, g_xh);
    cudaGetSymbolAddress((void**)&Wqh, g_Wqh);
    cudaGetSymbolAddress((void**)&Wkh, g_Wkh);
    cudaGetSymbolAddress((void**)&Wvh, g_Wvh);
    cudaGetSymbolAddress((void**)&Woh, g_Woh);

    const size_t attn_smem =
        (size_t)(128 * QLD + 2 * KVSTAGES * 64 * KVLD) * sizeof(__half);
    cudaFuncSetAttribute(attn_f16, cudaFuncAttributeMaxDynamicSharedMemorySize,
                         (int)attn_smem);
    cudaFuncSetAttribute(gemm_qkv, cudaFuncAttributeMaxDynamicSharedMemorySize, G_SMEM);
    cudaFuncSetAttribute(gemm_out, cudaFuncAttributeMaxDynamicSharedMemorySize, G_SMEM);

    cvt_all<<<(N16TOT + 255) / 256, 256>>>(x, Wq, Wk, Wv, Wo,
                                           xh, Wqh, Wkh, Wvh, Woh);

    const float QSCALE = 0.125f * 1.4426950408889634f;
    dim3 gq(768 / 128, MROWS / 128, 3);   // (6, 32, 3)
    gemm_qkv<<<gq, 256, G_SMEM>>>(xh, Wqh, Wkh, Wvh, bq, bk, bv, Qp, Kp, Vp, QSCALE);

    dim3 ga(SEQ / 128, NBH);              // (16, 24)
    attn_f16<<<ga, ATHREADS, attn_smem>>>(Qp, Kp, Vp, ctxp);

    dim3 gg(768 / 128, MROWS / 128);      // (6, 32)
    gemm_out<<<gg, 256, G_SMEM>>>(ctxp, Woh, bo, out);
}